// round 1
// baseline (speedup 1.0000x reference)
#include <cuda_runtime.h>
#include <math.h>
#include <stdint.h>

#define BB 32
#define TT 512
#define EE 256
#define UU 512
#define U3 1536
#define NBLK 64          // blocks per direction in recurrence
#define RGRID (2*NBLK)   // total recurrence blocks

// ---------------- device scratch (static; no runtime allocation) ------------
__device__ float    g_xproj[2][BB][TT][U3];   // ~201 MB: x@W + b_in per direction
__device__ float    g_h[2][2][BB][UU];        // [dir][buf][b][u] double-buffered state
__device__ unsigned g_cnt[2][TT];             // per-step barrier counters (memset to 0 each launch)

// ---------------- Kernel A: x_proj = emb[tokens] @ W + b_in -----------------
#define BM 128
#define BN 64
#define BK 16

__global__ void __launch_bounds__(256) xproj_kernel(
    const int* __restrict__ tokens,
    const float* __restrict__ emb,
    const float* __restrict__ W_fw, const float* __restrict__ b_in_fw,
    const float* __restrict__ W_bw, const float* __restrict__ b_in_bw)
{
    __shared__ float As[BK][BM];
    __shared__ float Bs[BK][BN];
    __shared__ int   toks[BM];

    const int d  = blockIdx.z;
    const float* __restrict__ Wp = d ? W_bw : W_fw;
    const float* __restrict__ bp = d ? b_in_bw : b_in_fw;
    const int n0 = blockIdx.x * BN;
    const int m0 = blockIdx.y * BM;
    const int tid = threadIdx.x;
    const int tx = tid & 15;       // 16 col-threads * 4 cols
    const int ty = tid >> 4;       // 16 row-threads * 8 rows

    if (tid < BM) toks[tid] = tokens[m0 + tid];
    __syncthreads();

    float acc[8][4];
#pragma unroll
    for (int i = 0; i < 8; i++)
#pragma unroll
        for (int j = 0; j < 4; j++) acc[i][j] = 0.f;

    for (int k0 = 0; k0 < EE; k0 += BK) {
        // A tile: gathered embedding rows, stored transposed As[k][m]
#pragma unroll
        for (int i = 0; i < 2; i++) {
            int id = tid * 2 + i;          // 0..511 float4 slots
            int m  = id >> 2;
            int kg = id & 3;
            float4 v = *(const float4*)(emb + (size_t)toks[m] * EE + k0 + kg * 4);
            As[kg*4+0][m] = v.x; As[kg*4+1][m] = v.y;
            As[kg*4+2][m] = v.z; As[kg*4+3][m] = v.w;
        }
        // B tile: W[k][n]
        {
            int k = tid >> 4, ng = tid & 15;
            *(float4*)&Bs[k][ng*4] =
                *(const float4*)(Wp + (size_t)(k0 + k) * U3 + n0 + ng * 4);
        }
        __syncthreads();
#pragma unroll
        for (int k = 0; k < BK; k++) {
            float4 a0 = *(const float4*)&As[k][ty*8];
            float4 a1 = *(const float4*)&As[k][ty*8+4];
            float4 b4 = *(const float4*)&Bs[k][tx*4];
            float a[8] = {a0.x,a0.y,a0.z,a0.w,a1.x,a1.y,a1.z,a1.w};
            float bb[4] = {b4.x,b4.y,b4.z,b4.w};
#pragma unroll
            for (int i = 0; i < 8; i++)
#pragma unroll
                for (int j = 0; j < 4; j++)
                    acc[i][j] = fmaf(a[i], bb[j], acc[i][j]);
        }
        __syncthreads();
    }

    // store with bias
    float4 bias = *(const float4*)(bp + n0 + tx * 4);
    float* gx = &g_xproj[0][0][0][0];
#pragma unroll
    for (int i = 0; i < 8; i++) {
        size_t m = (size_t)(m0 + ty * 8 + i);
        float4 v;
        v.x = acc[i][0] + bias.x; v.y = acc[i][1] + bias.y;
        v.z = acc[i][2] + bias.z; v.w = acc[i][3] + bias.w;
        *(float4*)(gx + ((size_t)d * (BB*TT) + m) * U3 + n0 + tx * 4) = v;
    }
}

// ---------------- Kernel B: persistent GRU recurrence -----------------------
// 128 blocks (64 per direction), 256 threads; block owns 8 hidden units.
// SMEM: h (swizzled float4, 64KB) + U-slice [24][512] (49KB) + hout (1KB).
#define SMEM_BYTES (32*128*16 + 24*512*4 + 32*8*4)

__global__ void __launch_bounds__(256, 1) gru_kernel(
    const int* __restrict__ tokens,
    const float* __restrict__ U_fw, const float* __restrict__ b_rec_fw,
    const float* __restrict__ U_bw, const float* __restrict__ b_rec_bw,
    float* __restrict__ out)
{
    extern __shared__ float smem[];
    float4* hs4  = (float4*)smem;                 // [32][128] float4, swizzled
    float*  Us   = smem + 32*128*4;               // [24][512], c = g*8 + uw
    float*  hout = Us + 24*512;                   // [32][8]

    const int bid = blockIdx.x;
    const int d   = bid >> 6;
    const int jb  = bid & (NBLK - 1);
    const int u0  = jb * 8;
    const int tid = threadIdx.x;
    const int uw  = tid >> 5;        // warp id -> local hidden unit
    const int b   = tid & 31;        // lane -> batch
    const int u   = u0 + uw;
    const int sw  = b & 7;

    const float* __restrict__ Uw = d ? U_bw : U_fw;
    const float* __restrict__ br = d ? b_rec_bw : b_rec_fw;

    // stage this block's 24 U-columns into SMEM once (reused for all 512 steps)
    for (int idx = tid; idx < 24 * 512; idx += 256) {
        int c = idx >> 9;
        int k = idx & 511;
        int g = c >> 3;
        int uu = u0 + (c & 7);
        Us[c * 512 + k] = Uw[(size_t)k * U3 + g * 512 + uu];
    }

    const float brz = br[0*512 + u];
    const float brr = br[1*512 + u];
    const float brh = br[2*512 + u];

    const float* gx = &g_xproj[0][0][0][0];
    const float4* uz4 = (const float4*)&Us[(0*8 + uw) * 512];
    const float4* ur4 = (const float4*)&Us[(1*8 + uw) * 512];
    const float4* uh4 = (const float4*)&Us[(2*8 + uw) * 512];

    __syncthreads();

    for (int ts = 0; ts < TT; ts++) {
        const int t   = d ? (TT - 1 - ts) : ts;
        const int buf = ts & 1;

        // stage h_prev into swizzled SMEM
        const float4* hp_g = (const float4*)&g_h[d][buf][0][0];
#pragma unroll
        for (int i = 0; i < 16; i++) {
            int id = tid + i * 256;        // 0..4095
            int bb = id >> 7;
            int kk = id & 127;
            hs4[bb * 128 + (kk ^ (bb & 7))] = hp_g[id];
        }
        // early loads (latency hidden behind the sync + dot loop)
        size_t xb = ((size_t)d * (BB*TT) + (size_t)b * TT + t) * U3;
        float xz = gx[xb + u];
        float xr = gx[xb + 512 + u];
        float xh = gx[xb + 1024 + u];
        int   mt = (tokens[b * TT + t] != 0);
        __syncthreads();

        // 512-wide dot products for gates z, r, h
        float az0=0.f, az1=0.f, ar0=0.f, ar1=0.f, ah0=0.f, ah1=0.f;
        const float4* hb = hs4 + b * 128;
#pragma unroll 8
        for (int kk = 0; kk < 128; kk++) {
            float4 h4 = hb[kk ^ sw];
            float4 z4 = uz4[kk];
            float4 r4 = ur4[kk];
            float4 c4 = uh4[kk];
            az0 = fmaf(h4.x, z4.x, az0); az1 = fmaf(h4.y, z4.y, az1);
            az0 = fmaf(h4.z, z4.z, az0); az1 = fmaf(h4.w, z4.w, az1);
            ar0 = fmaf(h4.x, r4.x, ar0); ar1 = fmaf(h4.y, r4.y, ar1);
            ar0 = fmaf(h4.z, r4.z, ar0); ar1 = fmaf(h4.w, r4.w, ar1);
            ah0 = fmaf(h4.x, c4.x, ah0); ah1 = fmaf(h4.y, c4.y, ah1);
            ah0 = fmaf(h4.z, c4.z, ah0); ah1 = fmaf(h4.w, c4.w, ah1);
        }
        float hz = az0 + az1 + brz;
        float hr = ar0 + ar1 + brr;
        float hh = ah0 + ah1 + brh;

        float z    = 1.f / (1.f + expf(-(xz + hz)));
        float r    = 1.f / (1.f + expf(-(xr + hr)));
        float cand = tanhf(xh + r * hh);
        float hp   = ((const float*)&hs4[b * 128 + ((u >> 2) ^ sw)])[u & 3];
        float hn   = z * hp + (1.f - z) * cand;
        if (!mt) hn = hp;

        hout[b * 8 + uw] = hn;
        __syncthreads();

        // coalesced writes: 32 rows x 8 floats -> state buffer + output slice
        if (tid < 64) {
            float4 v  = ((const float4*)hout)[tid];
            int row   = tid >> 1;
            int half  = tid & 1;
            *(float4*)&g_h[d][buf ^ 1][row][u0 + half * 4] = v;
            *(float4*)&out[((size_t)row * TT + t) * (2*UU) + (size_t)d * UU + u0 + half * 4] = v;
        }

        // inter-block barrier (per direction, per step); counters pre-zeroed
        if (ts + 1 < TT) {
            __syncthreads();
            if (tid == 0) {
                __threadfence();
                atomicAdd(&g_cnt[d][ts], 1u);
                volatile unsigned* c = &g_cnt[d][ts];
                while (*c < NBLK) { }
                __threadfence();
            }
            __syncthreads();
        }
    }
}

// ---------------- launch ----------------------------------------------------
extern "C" void kernel_launch(void* const* d_in, const int* in_sizes, int n_in,
                              void* d_out, int out_size)
{
    const int*   tokens   = (const int*)  d_in[0];
    const float* emb      = (const float*)d_in[1];
    const float* W_fw     = (const float*)d_in[2];
    const float* U_fw     = (const float*)d_in[3];
    const float* b_in_fw  = (const float*)d_in[4];
    const float* b_rec_fw = (const float*)d_in[5];
    const float* W_bw     = (const float*)d_in[6];
    const float* U_bw     = (const float*)d_in[7];
    const float* b_in_bw  = (const float*)d_in[8];
    const float* b_rec_bw = (const float*)d_in[9];
    float* out = (float*)d_out;

    void* p;
    cudaGetSymbolAddress(&p, g_h);
    cudaMemsetAsync(p, 0, sizeof(g_h));
    cudaGetSymbolAddress(&p, g_cnt);
    cudaMemsetAsync(p, 0, sizeof(g_cnt));

    dim3 gA(U3 / BN, (BB * TT) / BM, 2);
    xproj_kernel<<<gA, 256>>>(tokens, emb, W_fw, b_in_fw, W_bw, b_in_bw);

    cudaFuncSetAttribute(gru_kernel,
                         cudaFuncAttributeMaxDynamicSharedMemorySize, SMEM_BYTES);
    gru_kernel<<<RGRID, 256, SMEM_BYTES>>>(tokens, U_fw, b_rec_fw,
                                           U_bw, b_rec_bw, out);
}